// round 1
// baseline (speedup 1.0000x reference)
#include <cuda_runtime.h>
#include <cuda_bf16.h>

#define N_NODES_MAX 100000
#define D_FEAT 64
#define D4 (D_FEAT / 4)   // 16 float4 per row

// Scratch (allocation-free: device globals)
__device__ float g_x[N_NODES_MAX * D_FEAT];     // current polynomial term T_k(feat)
__device__ float g_agg[N_NODES_MAX * D_FEAT];   // scatter accumulator
__device__ float g_deg[N_NODES_MAX];
__device__ float g_dinv[N_NODES_MAX];

// ---------------------------------------------------------------------------
__global__ void k_zero_deg(int n) {
    int i = blockIdx.x * blockDim.x + threadIdx.x;
    if (i < n) g_deg[i] = 0.0f;
}

__global__ void k_count_deg(const int* __restrict__ dst, int ne) {
    int e = blockIdx.x * blockDim.x + threadIdx.x;
    if (e < ne) atomicAdd(&g_deg[dst[e]], 1.0f);
}

__global__ void k_dinv(int n) {
    int i = blockIdx.x * blockDim.x + threadIdx.x;
    if (i < n) g_dinv[i] = rsqrtf(fmaxf(g_deg[i], 1.0f));
}

// x = feat; h = theta0 * feat; agg = 0   (one thread per float4)
__global__ void k_init(const float* __restrict__ feat,
                       const float* __restrict__ theta,
                       float* __restrict__ h, int n4) {
    int t = blockIdx.x * blockDim.x + threadIdx.x;
    if (t >= n4) return;
    float4 f = reinterpret_cast<const float4*>(feat)[t];
    reinterpret_cast<float4*>(g_x)[t] = f;
    float t0 = theta[0];
    float4 hh = make_float4(t0 * f.x, t0 * f.y, t0 * f.z, t0 * f.w);
    reinterpret_cast<float4*>(h)[t] = hh;
    reinterpret_cast<float4*>(g_agg)[t] = make_float4(0.f, 0.f, 0.f, 0.f);
}

// Scatter: agg[dst] += x[src] * dinv[src].  16 threads per edge (one float4 each).
__global__ void k_scatter(const int* __restrict__ src,
                          const int* __restrict__ dst, int ne) {
    long long gid = (long long)blockIdx.x * blockDim.x + threadIdx.x;
    int e = (int)(gid >> 4);
    int q = (int)(gid & 15);
    if (e >= ne) return;
    int s = __ldg(&src[e]);
    int d = __ldg(&dst[e]);
    float di = __ldg(&g_dinv[s]);
    float4 v = reinterpret_cast<const float4*>(g_x)[s * D4 + q];
    v.x *= di; v.y *= di; v.z *= di; v.w *= di;
    float* addr = &g_agg[d * D_FEAT + q * 4];
    asm volatile("red.global.add.v4.f32 [%0], {%1, %2, %3, %4};"
                 :: "l"(addr), "f"(v.x), "f"(v.y), "f"(v.z), "f"(v.w)
                 : "memory");
}

// x = x - agg*dinv;  h += theta_k * x;  agg = 0  (one thread per float4)
__global__ void k_apply(float* __restrict__ h,
                        const float* __restrict__ theta, int k, int n4) {
    int t = blockIdx.x * blockDim.x + threadIdx.x;
    if (t >= n4) return;
    int node = t >> 4;  // D4 == 16
    float di = __ldg(&g_dinv[node]);
    float4 x = reinterpret_cast<float4*>(g_x)[t];
    float4 a = reinterpret_cast<float4*>(g_agg)[t];
    x.x -= a.x * di;
    x.y -= a.y * di;
    x.z -= a.z * di;
    x.w -= a.w * di;
    reinterpret_cast<float4*>(g_x)[t] = x;
    float th = theta[k];
    float4 hh = reinterpret_cast<float4*>(h)[t];
    hh.x += th * x.x;
    hh.y += th * x.y;
    hh.z += th * x.z;
    hh.w += th * x.w;
    reinterpret_cast<float4*>(h)[t] = hh;
    reinterpret_cast<float4*>(g_agg)[t] = make_float4(0.f, 0.f, 0.f, 0.f);
}

// ---------------------------------------------------------------------------
extern "C" void kernel_launch(void* const* d_in, const int* in_sizes, int n_in,
                              void* d_out, int out_size) {
    const float* feat  = (const float*)d_in[0];
    const float* theta = (const float*)d_in[1];
    const int*   src   = (const int*)d_in[2];
    const int*   dst   = (const int*)d_in[3];
    float* h = (float*)d_out;

    const int n  = in_sizes[0] / D_FEAT;   // nodes
    const int ne = in_sizes[2];            // edges
    const int K  = in_sizes[1];            // theta length (5)
    const int n4 = n * D4;                 // float4 count

    const int T = 256;
    k_zero_deg<<<(n + T - 1) / T, T>>>(n);
    k_count_deg<<<(ne + T - 1) / T, T>>>(dst, ne);
    k_dinv<<<(n + T - 1) / T, T>>>(n);
    k_init<<<(n4 + T - 1) / T, T>>>(feat, theta, h, n4);

    long long scatter_threads = (long long)ne * 16;
    int scatter_blocks = (int)((scatter_threads + T - 1) / T);

    for (int k = 1; k < K; k++) {
        k_scatter<<<scatter_blocks, T>>>(src, dst, ne);
        k_apply<<<(n4 + T - 1) / T, T>>>(h, theta, k, n4);
    }
}